// round 4
// baseline (speedup 1.0000x reference)
#include <cuda_runtime.h>
#include <cstdint>

// Problem constants
#define Bv 8
#define Vv 256
#define Hv 128
#define ROWS (Bv*Vv)          // 2048
#define H4 (Hv/4)             // 32 float4 per row

typedef unsigned long long ull;

// Intermediates (device globals; no allocation allowed)
__device__ float g_h0[ROWS*Hv];                 // silu(h @ W_pre + b_pre)
__device__ float g_sk[ROWS*Hv];                 // silu(h @ W_skip + b_skip)
__device__ float g_part[2*ROWS*Hv];             // neigh partial maxes (2 j-halves)

__device__ __forceinline__ float silu_f(float x) {
    return x * (1.0f / (1.0f + __expf(-x)));
}

__device__ __forceinline__ void cp16(uint32_t dst, const void* src) {
    asm volatile("cp.async.cg.shared.global [%0], [%1], 16;" :: "r"(dst), "l"(src));
}
__device__ __forceinline__ void cp_commit() {
    asm volatile("cp.async.commit_group;");
}

__device__ __forceinline__ ull ffma2(ull a, ull b, ull c) {
    ull d;
    asm("fma.rn.f32x2 %0, %1, %2, %3;" : "=l"(d) : "l"(a), "l"(b), "l"(c));
    return d;
}
__device__ __forceinline__ ull pack2(float x, float y) {
    ull d; asm("mov.b64 %0, {%1, %2};" : "=l"(d) : "f"(x), "f"(y)); return d;
}
__device__ __forceinline__ float2 unpack2(ull v) {
    float2 r; asm("mov.b64 {%0, %1}, %2;" : "=f"(r.x), "=f"(r.y) : "l"(v)); return r;
}

// ---------------------------------------------------------------------------
// Kernel A: h0 = silu(h @ W_pre + b_pre), sk = silu(h @ W_skip + b_skip)
// 128 blocks x 256 threads, 16 rows/block. Activations transposed in smem
// (aT[k][row]) so 4 rows = one LDS.128 = two f32x2 pairs. Each thread:
// 8 rows x 1 col x 2 matrices via packed FFMA2. W streamed by cp.async in
// 16-k chunks, double-buffered.
// ---------------------------------------------------------------------------
__global__ void __launch_bounds__(256) pre_kernel(
    const float* __restrict__ h,
    const float* __restrict__ Wpre,  const float* __restrict__ bpre,
    const float* __restrict__ Wskip, const float* __restrict__ bskip)
{
    __shared__ float hsT[Hv][16];        // 8 KB  : hsT[k][r]
    __shared__ float WA[2][16 * Hv];     // 16 KB : W_pre chunk (16 k x 128 c)
    __shared__ float WB[2][16 * Hv];     // 16 KB : W_skip chunk

    const int tid = threadIdx.x;
    const int c   = tid & 127;
    const int r0  = (tid >> 7) * 8;      // 0 or 8
    const int row0 = blockIdx.x * 16;

    // Stage transposed h rows: 512 float4, 2 per thread.
    const float4* h4 = (const float4*)h;
#pragma unroll
    for (int x = tid; x < 512; x += 256) {
        const int r = x & 15, k4 = x >> 4;
        float4 v = h4[(row0 + r) * H4 + k4];
        hsT[k4 * 4 + 0][r] = v.x;
        hsT[k4 * 4 + 1][r] = v.y;
        hsT[k4 * 4 + 2][r] = v.z;
        hsT[k4 * 4 + 3][r] = v.w;
    }

    const float4* WAg = (const float4*)Wpre;
    const float4* WBg = (const float4*)Wskip;
    const uint32_t sWA = (uint32_t)__cvta_generic_to_shared(&WA[0][0]);
    const uint32_t sWB = (uint32_t)__cvta_generic_to_shared(&WB[0][0]);

    // one chunk = 16 k x 128 c = 512 float4 per matrix; 2 cp16/thread/matrix
    auto issue = [&](int ch) {
        const int buf = ch & 1;
#pragma unroll
        for (int r = 0; r < 2; r++) {
            const int x = r * 256 + tid;
            cp16(sWA + (buf * 512 + x) * 16, WAg + ch * 512 + x);
            cp16(sWB + (buf * 512 + x) * 16, WBg + ch * 512 + x);
        }
        cp_commit();
    };
    issue(0);
    issue(1);

    ull accA[4], accB[4];
    {
        const float bA = bpre[c], bB = bskip[c];
#pragma unroll
        for (int p = 0; p < 4; p++) { accA[p] = pack2(bA, bA); accB[p] = pack2(bB, bB); }
    }

    for (int ch = 0; ch < 8; ch++) {
        if (ch == 7) asm volatile("cp.async.wait_group 0;");
        else         asm volatile("cp.async.wait_group 1;");
        __syncthreads();                      // covers hsT staging on ch=0

        const float* wAc = &WA[ch & 1][0];
        const float* wBc = &WB[ch & 1][0];
        const int kbase = ch * 16;
#pragma unroll
        for (int kk = 0; kk < 16; kk++) {
            const int k = kbase + kk;
            ulonglong2 hLo = *(const ulonglong2*)&hsT[k][r0];      // rows r0..r0+3
            ulonglong2 hHi = *(const ulonglong2*)&hsT[k][r0 + 4];  // rows r0+4..r0+7
            const float wa = wAc[kk * Hv + c];
            const float wb = wBc[kk * Hv + c];
            const ull wa2 = pack2(wa, wa);
            const ull wb2 = pack2(wb, wb);
            accA[0] = ffma2(hLo.x, wa2, accA[0]);
            accA[1] = ffma2(hLo.y, wa2, accA[1]);
            accA[2] = ffma2(hHi.x, wa2, accA[2]);
            accA[3] = ffma2(hHi.y, wa2, accA[3]);
            accB[0] = ffma2(hLo.x, wb2, accB[0]);
            accB[1] = ffma2(hLo.y, wb2, accB[1]);
            accB[2] = ffma2(hHi.x, wb2, accB[2]);
            accB[3] = ffma2(hHi.y, wb2, accB[3]);
        }

        __syncthreads();
        if (ch + 2 < 8) issue(ch + 2);
    }

#pragma unroll
    for (int p = 0; p < 4; p++) {
        const int row = row0 + r0 + 2 * p;
        float2 vA = unpack2(accA[p]);
        float2 vB = unpack2(accB[p]);
        g_h0[row * Hv + c]       = silu_f(vA.x);
        g_h0[(row + 1) * Hv + c] = silu_f(vA.y);
        g_sk[row * Hv + c]       = silu_f(vB.x);
        g_sk[(row + 1) * Hv + c] = silu_f(vB.y);
    }
}

// ---------------------------------------------------------------------------
// Kernel B (dominant): partial neigh max over a 128-wide j-half.
// 512 blocks (b x 32 i-tiles x 2 j-halves) x 256 threads -> ALL resident
// (36 KB smem/block, no wave tail). h0 staged via cp.async double buffer.
// ---------------------------------------------------------------------------
__global__ void __launch_bounds__(256) agg_kernel(
    const float* __restrict__ e,
    const int*   __restrict__ graph)
{
    __shared__ float4 h0s[2][32 * H4];   // 2 x 16 KB
    __shared__ int    gsh[8][128];       // 4 KB

    const int tid  = threadIdx.x;
    const int hq   = tid & 31;           // float4 index in H
    const int isub = tid >> 5;           // 0..7
    const int b    = blockIdx.x >> 6;
    const int rem  = blockIdx.x & 63;
    const int i0   = (rem >> 1) * 8;
    const int jh   = rem & 1;
    const int j0   = jh * 128;
    const int i    = i0 + isub;

    // stage graph mask for this (i-tile, j-half): 1024 ints, 4/thread
#pragma unroll
    for (int x = tid; x < 8 * 128; x += 256) {
        gsh[x >> 7][x & 127] = graph[(b * Vv + i0 + (x >> 7)) * Vv + j0 + (x & 127)];
    }

    const float4* H0 = (const float4*)g_h0 + b * Vv * H4 + j0 * H4;
    const uint32_t sb0 = (uint32_t)__cvta_generic_to_shared(&h0s[0][0]);
    const uint32_t sb1 = (uint32_t)__cvta_generic_to_shared(&h0s[1][0]);

    // issue chunk c (32 j x 32 q = 1024 float4; 4 cp.async per thread)
    auto issue = [&](int c) {
        const uint32_t sb = (c & 1) ? sb1 : sb0;
#pragma unroll
        for (int r = 0; r < 4; r++) {
            const int x = r * 256 + tid;
            cp16(sb + x * 16, (const void*)(H0 + c * 1024 + x));
        }
        cp_commit();
    };
    issue(0);
    issue(1);

    const float4* Ep = (const float4*)e + ((size_t)(b * Vv + i) * Vv + j0) * H4 + hq;

    const float NEG_INF = __int_as_float(0xff800000);
    float4 acc = make_float4(NEG_INF, NEG_INF, NEG_INF, NEG_INF);

    for (int c = 0; c < 4; c++) {
        if (c == 3) asm volatile("cp.async.wait_group 0;");
        else        asm volatile("cp.async.wait_group 1;");
        __syncthreads();

        const float4* hb = h0s[c & 1];
        const int*    gm = &gsh[isub][c * 32];

#pragma unroll 8
        for (int jj = 0; jj < 32; jj++) {
            float4 ev = Ep[jj * H4];
            float4 hv = hb[jj * H4 + hq];
            if (gm[jj] != 0) { hv.x = 0.f; hv.y = 0.f; hv.z = 0.f; hv.w = 0.f; }
            acc.x = fmaxf(acc.x, ev.x * hv.x);
            acc.y = fmaxf(acc.y, ev.y * hv.y);
            acc.z = fmaxf(acc.z, ev.z * hv.z);
            acc.w = fmaxf(acc.w, ev.w * hv.w);
        }
        Ep += 32 * H4;

        __syncthreads();
        if (c + 2 < 4) issue(c + 2);
    }

    ((float4*)g_part)[((size_t)jh * ROWS + b * Vv + i) * H4 + hq] = acc;
}

// ---------------------------------------------------------------------------
// Kernel C: out = silu( sk + silu([h0,neigh] @ W_post + b_post) )
// 128 blocks x 256 threads, 16 rows/block. Concat activations transposed in
// smem (aT[k][row], k in [0,256)), neigh = max of partials folded in during
// staging. Same FFMA2 + cp.async W pipeline as pre.
// ---------------------------------------------------------------------------
__global__ void __launch_bounds__(256) post_kernel(
    const float* __restrict__ Wpost, const float* __restrict__ bpost,
    float* __restrict__ out)
{
    __shared__ float aT[2 * Hv][16];     // 16 KB : aT[k][r], k<128 -> h0, k>=128 -> neigh
    __shared__ float WP[2][16 * Hv];     // 16 KB : W_post chunk

    const int tid = threadIdx.x;
    const int c   = tid & 127;
    const int r0  = (tid >> 7) * 8;
    const int row0 = blockIdx.x * 16;

    // Stage transposed h0 and neigh(= max of partial halves): 2 float4 each/thread.
    const float4* h04 = (const float4*)g_h0;
    const float4* gp  = (const float4*)g_part;
#pragma unroll
    for (int x = tid; x < 512; x += 256) {
        const int r = x & 15, k4 = x >> 4;
        float4 v = h04[(row0 + r) * H4 + k4];
        aT[k4 * 4 + 0][r] = v.x;
        aT[k4 * 4 + 1][r] = v.y;
        aT[k4 * 4 + 2][r] = v.z;
        aT[k4 * 4 + 3][r] = v.w;
        float4 p0 = gp[(row0 + r) * H4 + k4];
        float4 p1 = gp[((size_t)ROWS + row0 + r) * H4 + k4];
        aT[Hv + k4 * 4 + 0][r] = fmaxf(p0.x, p1.x);
        aT[Hv + k4 * 4 + 1][r] = fmaxf(p0.y, p1.y);
        aT[Hv + k4 * 4 + 2][r] = fmaxf(p0.z, p1.z);
        aT[Hv + k4 * 4 + 3][r] = fmaxf(p0.w, p1.w);
    }

    const float4* Wg = (const float4*)Wpost;   // 256 k x 128 c
    const uint32_t sW = (uint32_t)__cvta_generic_to_shared(&WP[0][0]);

    auto issue = [&](int ch) {
        const int buf = ch & 1;
#pragma unroll
        for (int r = 0; r < 2; r++) {
            const int x = r * 256 + tid;
            cp16(sW + (buf * 512 + x) * 16, Wg + ch * 512 + x);
        }
        cp_commit();
    };
    issue(0);
    issue(1);

    ull acc[4];
    {
        const float bP = bpost[c];
#pragma unroll
        for (int p = 0; p < 4; p++) acc[p] = pack2(bP, bP);
    }

    for (int ch = 0; ch < 16; ch++) {
        if (ch == 15) asm volatile("cp.async.wait_group 0;");
        else          asm volatile("cp.async.wait_group 1;");
        __syncthreads();                    // covers aT staging on ch=0

        const float* wc = &WP[ch & 1][0];
        const int kbase = ch * 16;
#pragma unroll
        for (int kk = 0; kk < 16; kk++) {
            const int k = kbase + kk;
            ulonglong2 aLo = *(const ulonglong2*)&aT[k][r0];
            ulonglong2 aHi = *(const ulonglong2*)&aT[k][r0 + 4];
            const float w = wc[kk * Hv + c];
            const ull w2 = pack2(w, w);
            acc[0] = ffma2(aLo.x, w2, acc[0]);
            acc[1] = ffma2(aLo.y, w2, acc[1]);
            acc[2] = ffma2(aHi.x, w2, acc[2]);
            acc[3] = ffma2(aHi.y, w2, acc[3]);
        }

        __syncthreads();
        if (ch + 2 < 16) issue(ch + 2);
    }

#pragma unroll
    for (int p = 0; p < 4; p++) {
        const int row = row0 + r0 + 2 * p;
        float2 v = unpack2(acc[p]);
        out[row * Hv + c]       = silu_f(g_sk[row * Hv + c]       + silu_f(v.x));
        out[(row + 1) * Hv + c] = silu_f(g_sk[(row + 1) * Hv + c] + silu_f(v.y));
    }
}

// ---------------------------------------------------------------------------
extern "C" void kernel_launch(void* const* d_in, const int* in_sizes, int n_in,
                              void* d_out, int out_size)
{
    const float* h     = (const float*)d_in[0];
    const float* e     = (const float*)d_in[1];
    const int*   graph = (const int*)  d_in[2];
    const float* Wpre  = (const float*)d_in[3];
    const float* bpre  = (const float*)d_in[4];
    const float* Wpost = (const float*)d_in[5];
    const float* bpost = (const float*)d_in[6];
    const float* Wskip = (const float*)d_in[7];
    const float* bskip = (const float*)d_in[8];
    float* out = (float*)d_out;

    pre_kernel<<<ROWS / 16, 256>>>(h, Wpre, bpre, Wskip, bskip);
    agg_kernel<<<(ROWS / 8) * 2, 256>>>(e, graph);
    post_kernel<<<ROWS / 16, 256>>>(Wpost, bpost, out);
}